// round 6
// baseline (speedup 1.0000x reference)
#include <cuda_runtime.h>

#define TL 512
#define WN 16
#define HD 64
#define DM 512
#define ATT_SZ (1024 * DM)

#define INV2PI 0.15915494309189535f
#define MAGIC  12582912.0f            // 1.5 * 2^23
#define C2PI_A 6.2831854820251465f

// ---------------- static scratch (no allocation) ---------------------------
__device__ float g_freq [16*TL*WN];   // [bh][t][w]
__device__ float g_phase[16*TL*WN];
__device__ float g_amp  [16*TL*WN];
__device__ float g_v    [16*TL*HD];   // [bh][t][d]
__device__ float g_att8 [8*ATT_SZ];   // attn@V partials, 8 k-slots

// ---------------- stage 1: projections, 64x32 tiles, 128 thr, 448 CTAs -----
// grid (28, 16): n-tiles 0-3 freq, 4-7 phase, 8-11 amp, 12-27 v
__global__ __launch_bounds__(128)
void proj3_kernel(const float* __restrict__ x,
                  const float* __restrict__ Wf, const float* __restrict__ bf,
                  const float* __restrict__ Wp, const float* __restrict__ bp,
                  const float* __restrict__ Wa, const float* __restrict__ ba,
                  const float* __restrict__ Wv, const float* __restrict__ bv)
{
    __shared__ float As[2][16][68];
    __shared__ float Ws[2][16][36];

    const int nt = blockIdx.x;
    const int m0 = blockIdx.y * 64;
    const float* W; const float* bias; int ldw, nc0, kind;
    if      (nt < 4)  { W = Wf; bias = bf; ldw = 128; nc0 = nt*32;        kind = 0; }
    else if (nt < 8)  { W = Wp; bias = bp; ldw = 128; nc0 = (nt-4)*32;    kind = 1; }
    else if (nt < 12) { W = Wa; bias = ba; ldw = 128; nc0 = (nt-8)*32;    kind = 2; }
    else              { W = Wv; bias = bv; ldw = 512; nc0 = (nt-12)*32;   kind = 3; }

    const int tid = threadIdx.x;
    const int lm  = tid >> 1;          // A row (0..63)
    const int lk8 = (tid & 1) << 3;    // A k offset (0 or 8)
    const int wr  = tid >> 3;          // W k row (0..15)
    const int wc4 = (tid & 7) << 2;    // W n offset
    const int tx  = tid & 7;           // n group (0..7)
    const int ty  = tid >> 3;          // m group (0..15)

    const float* Ar = x + (size_t)(m0 + lm) * DM + lk8;
    const float* Wb = W + (size_t)wr * ldw + nc0 + wc4;

    float4 a0 = *(const float4*)(Ar);
    float4 a1 = *(const float4*)(Ar + 4);
    float4 w  = *(const float4*)(Wb);

    float acc[4][4] = {};
    int buf = 0;
#pragma unroll 1
    for (int k0 = 0; k0 < 512; k0 += 16) {
        As[buf][lk8 + 0][lm] = a0.x;
        As[buf][lk8 + 1][lm] = a0.y;
        As[buf][lk8 + 2][lm] = a0.z;
        As[buf][lk8 + 3][lm] = a0.w;
        As[buf][lk8 + 4][lm] = a1.x;
        As[buf][lk8 + 5][lm] = a1.y;
        As[buf][lk8 + 6][lm] = a1.z;
        As[buf][lk8 + 7][lm] = a1.w;
        *(float4*)&Ws[buf][wr][wc4] = w;
        __syncthreads();
        if (k0 + 16 < 512) {
            a0 = *(const float4*)(Ar + k0 + 16);
            a1 = *(const float4*)(Ar + k0 + 20);
            w  = *(const float4*)(Wb + (size_t)(k0 + 16) * ldw);
        }
#pragma unroll
        for (int kk = 0; kk < 16; kk++) {
            float4 a4 = *(const float4*)&As[buf][kk][ty << 2];
            float4 b4 = *(const float4*)&Ws[buf][kk][tx << 2];
            acc[0][0] = fmaf(a4.x, b4.x, acc[0][0]);
            acc[0][1] = fmaf(a4.x, b4.y, acc[0][1]);
            acc[0][2] = fmaf(a4.x, b4.z, acc[0][2]);
            acc[0][3] = fmaf(a4.x, b4.w, acc[0][3]);
            acc[1][0] = fmaf(a4.y, b4.x, acc[1][0]);
            acc[1][1] = fmaf(a4.y, b4.y, acc[1][1]);
            acc[1][2] = fmaf(a4.y, b4.z, acc[1][2]);
            acc[1][3] = fmaf(a4.y, b4.w, acc[1][3]);
            acc[2][0] = fmaf(a4.z, b4.x, acc[2][0]);
            acc[2][1] = fmaf(a4.z, b4.y, acc[2][1]);
            acc[2][2] = fmaf(a4.z, b4.z, acc[2][2]);
            acc[2][3] = fmaf(a4.z, b4.w, acc[2][3]);
            acc[3][0] = fmaf(a4.w, b4.x, acc[3][0]);
            acc[3][1] = fmaf(a4.w, b4.y, acc[3][1]);
            acc[3][2] = fmaf(a4.w, b4.z, acc[3][2]);
            acc[3][3] = fmaf(a4.w, b4.w, acc[3][3]);
        }
        buf ^= 1;
    }

#pragma unroll
    for (int i = 0; i < 4; i++) {
#pragma unroll
        for (int j = 0; j < 4; j++) {
            int m = m0 + (ty << 2) + i;
            int n = nc0 + (tx << 2) + j;
            float c = acc[i][j] + bias[n];
            int b = m >> 9, t = m & 511;
            if (kind == 3) {
                int h = n >> 6, d = n & 63;
                g_v[(((size_t)(b*8 + h) * TL) + t) * HD + d] = c;
            } else {
                int h = n >> 4, w_ = n & 15;
                size_t idx = (((size_t)(b*8 + h) * TL) + t) * WN + w_;
                if (kind == 0)      g_freq[idx]  = c;
                else if (kind == 1) g_phase[idx] = c;
                else {
                    float sp = fmaxf(c, 0.0f) + log1pf(expf(-fabsf(c)));
                    g_amp[idx] = sp + 1e-8f;
                }
            }
        }
    }
}

// ---------------- stage 2: attention, ONE 64x64 k-tile per CTA -------------
// grid (16 bh, 8 qt, 8 s); live iff s <= qt  (576 live CTAs, equal work)
#define WAVE(FK, PK, AK, W_) {                                   \
    float dw  = fq[W_] - (FK);                                   \
    float dp  = pq[W_] - (PK);                                   \
    float arg = fmaf(dw, dtv, dp);                               \
    float nn  = fmaf(arg, INV2PI, MAGIC) - MAGIC;                \
    float rr  = fmaf(nn, -C2PI_A, arg);                          \
    float cs  = __cosf(rr);                                      \
    float pp  = aq[W_] * (AK);                                   \
    dacc += pp;                                                  \
    cacc  = fmaf(pp, cs, cacc); }

__global__ __launch_bounds__(256, 2)
void attn8_kernel()
{
    const int bh = blockIdx.x;               // b*8+h
    const int qt = blockIdx.y;               // q tile (0..7)
    const int s  = blockIdx.z;               // k tile slot (0..7)
    if (s > qt) return;                      // dead CTA

    __shared__ float s_fpa[64 * 52];   // per k row: 16 f | 16 p | 16 a | pad 4
    __shared__ float s_s2p[64 * 4];    // per k row: 4 partial sums of a^2
    __shared__ float s_att[64 * 68];   // [k][q], transposed
    __shared__ float s_v  [64 * 68];   // [k][d]

    const int kt  = s * 64;
    const int tid = threadIdx.x;
    const int qa = tid >> 2;                 // phase A q row (0..63)
    const int g  = tid & 3;                  // phase A k lane
    const int ty = tid >> 4;                 // phase B q group
    const int tx = tid & 15;                 // phase B d group
    const int qglob = qt * 64 + qa;
    const int b = bh >> 3, h = bh & 7;

    // q-side params in registers
    float fq[16], pq[16], aq[16];
    {
        const float4* f4 = (const float4*)(g_freq  + (((size_t)bh*TL) + qglob) * WN);
        const float4* p4 = (const float4*)(g_phase + (((size_t)bh*TL) + qglob) * WN);
        const float4* a4 = (const float4*)(g_amp   + (((size_t)bh*TL) + qglob) * WN);
#pragma unroll
        for (int i = 0; i < 4; i++) {
            float4 t;
            t = f4[i]; fq[4*i]=t.x; fq[4*i+1]=t.y; fq[4*i+2]=t.z; fq[4*i+3]=t.w;
            t = p4[i]; pq[4*i]=t.x; pq[4*i+1]=t.y; pq[4*i+2]=t.z; pq[4*i+3]=t.w;
            t = a4[i]; aq[4*i]=t.x; aq[4*i+1]=t.y; aq[4*i+2]=t.z; aq[4*i+3]=t.w;
        }
    }
    float s2q = 0.f;
#pragma unroll
    for (int i = 0; i < 16; i++) s2q = fmaf(aq[i], aq[i], s2q);

    // ---- stage k-tile ----
    {
        int row = tid >> 2, c4 = (tid & 3) << 2;
        size_t base = ((size_t)bh * TL + (kt + row)) * WN + c4;
        float4 f = *(const float4*)(g_freq  + base);
        float4 p = *(const float4*)(g_phase + base);
        float4 a = *(const float4*)(g_amp   + base);
        *(float4*)&s_fpa[row*52 +      c4] = f;
        *(float4*)&s_fpa[row*52 + 16 + c4] = p;
        *(float4*)&s_fpa[row*52 + 32 + c4] = a;
        s_s2p[row*4 + (tid & 3)] = a.x*a.x + a.y*a.y + a.z*a.z + a.w*a.w;
#pragma unroll
        for (int i = 0; i < 4; i++) {
            int l = tid + i * 256;
            int r = l >> 4, cc = (l & 15) << 2;
            *(float4*)&s_v[r*68 + cc] =
                *(const float4*)(g_v + ((size_t)bh*TL + (kt + r)) * HD + cc);
        }
    }
    __syncthreads();

    // ---- phase A: attn tile ----
#pragma unroll 1
    for (int j = 0; j < 16; j++) {
        int kl = g + (j << 2);
        int kg = kt + kl;
        float attv = 0.f;
        if (kg <= qglob) {
            const float dtv = (float)(qglob - kg);
            const float* fk = &s_fpa[kl * 52];
            float4 s2p = *(const float4*)&s_s2p[kl * 4];
            float s2k = (s2p.x + s2p.y) + (s2p.z + s2p.w);
            float cacc = 0.f, dacc = 0.f;
#pragma unroll
            for (int g4 = 0; g4 < 4; g4++) {
                float4 f4 = *(const float4*)(fk +      (g4 << 2));
                float4 p4 = *(const float4*)(fk + 16 + (g4 << 2));
                float4 a4 = *(const float4*)(fk + 32 + (g4 << 2));
                WAVE(f4.x, p4.x, a4.x, (g4<<2) + 0);
                WAVE(f4.y, p4.y, a4.y, (g4<<2) + 1);
                WAVE(f4.z, p4.z, a4.z, (g4<<2) + 2);
                WAVE(f4.w, p4.w, a4.w, (g4<<2) + 3);
            }
            float S  = s2q + s2k;
            float it = fmaf(2.f, cacc, S);
            float en = fmaf(2.f, dacc, S) + 1e-8f;
            attv = __fdividef(it, en);
        }
        s_att[kl * 68 + qa] = attv;
    }
    __syncthreads();

    // ---- phase B: acc = attn_tile @ V_tile ----
    float acc[4][4] = {};
#pragma unroll 4
    for (int kk = 0; kk < 64; kk++) {
        float4 a4 = *(const float4*)&s_att[kk*68 + (ty << 2)];
        float4 v4 = *(const float4*)&s_v  [kk*68 + (tx << 2)];
        acc[0][0] = fmaf(a4.x, v4.x, acc[0][0]);
        acc[0][1] = fmaf(a4.x, v4.y, acc[0][1]);
        acc[0][2] = fmaf(a4.x, v4.z, acc[0][2]);
        acc[0][3] = fmaf(a4.x, v4.w, acc[0][3]);
        acc[1][0] = fmaf(a4.y, v4.x, acc[1][0]);
        acc[1][1] = fmaf(a4.y, v4.y, acc[1][1]);
        acc[1][2] = fmaf(a4.y, v4.z, acc[1][2]);
        acc[1][3] = fmaf(a4.y, v4.w, acc[1][3]);
        acc[2][0] = fmaf(a4.z, v4.x, acc[2][0]);
        acc[2][1] = fmaf(a4.z, v4.y, acc[2][1]);
        acc[2][2] = fmaf(a4.z, v4.z, acc[2][2]);
        acc[2][3] = fmaf(a4.z, v4.w, acc[2][3]);
        acc[3][0] = fmaf(a4.w, v4.x, acc[3][0]);
        acc[3][1] = fmaf(a4.w, v4.y, acc[3][1]);
        acc[3][2] = fmaf(a4.w, v4.z, acc[3][2]);
        acc[3][3] = fmaf(a4.w, v4.w, acc[3][3]);
    }

    // ---- epilogue: write partial tile to slot s ----
    float* dst = g_att8 + (size_t)s * ATT_SZ;
#pragma unroll
    for (int i = 0; i < 4; i++) {
        int row = qt * 64 + (ty << 2) + i;
        *(float4*)&dst[((size_t)(b * TL + row)) * DM + h * HD + (tx << 2)] =
            make_float4(acc[i][0], acc[i][1], acc[i][2], acc[i][3]);
    }
}

// ---------------- stage 3: output projection, 64x32 tiles, 128 thr ---------
// A[m][k] = sum over slots 0..qt of g_att8; bias fused; 256 CTAs
__global__ __launch_bounds__(128)
void outp8_kernel(const float* __restrict__ Wo,
                  const float* __restrict__ bo,
                  float* __restrict__ y)
{
    __shared__ float As[2][16][68];
    __shared__ float Ws[2][16][36];

    const int n0 = blockIdx.x * 32;
    const int m0 = blockIdx.y * 64;
    const int nsum = ((m0 & 511) >> 6) + 1;   // qt+1 partial buffers

    const int tid = threadIdx.x;
    const int lm  = tid >> 1;
    const int lk8 = (tid & 1) << 3;
    const int wr  = tid >> 3;
    const int wc4 = (tid & 7) << 2;
    const int tx  = tid & 7;
    const int ty  = tid >> 3;

    const size_t abase = (size_t)(m0 + lm) * DM + lk8;
    const float* Wb = Wo + (size_t)wr * DM + n0 + wc4;

    float4 a0, a1, w;
    {
        a0 = make_float4(0.f,0.f,0.f,0.f); a1 = a0;
#pragma unroll 1
        for (int jb = 0; jb < nsum; jb++) {
            const float* p = g_att8 + (size_t)jb * ATT_SZ + abase;
            float4 t0 = *(const float4*)p;
            float4 t1 = *(const float4*)(p + 4);
            a0.x += t0.x; a0.y += t0.y; a0.z += t0.z; a0.w += t0.w;
            a1.x += t1.x; a1.y += t1.y; a1.z += t1.z; a1.w += t1.w;
        }
        w = *(const float4*)(Wb);
    }

    float acc[4][4] = {};
    int buf = 0;
#pragma unroll 1
    for (int k0 = 0; k0 < 512; k0 += 16) {
        As[buf][lk8 + 0][lm] = a0.x;
        As[buf][lk8 + 1][lm] = a0.y;
        As[buf][lk8 + 2][lm] = a0.z;
        As[buf][lk8 + 3][lm] = a0.w;
        As[buf][lk8 + 4][lm] = a1.x;
        As[buf][lk8 + 5][lm] = a1.y;
        As[buf][lk8 + 6][lm] = a1.z;
        As[buf][lk8 + 7][lm] = a1.w;
        *(float4*)&Ws[buf][wr][wc4] = w;
        __syncthreads();
        if (k0 + 16 < 512) {
            a0 = make_float4(0.f,0.f,0.f,0.f); a1 = a0;
#pragma unroll 1
            for (int jb = 0; jb < nsum; jb++) {
                const float* p = g_att8 + (size_t)jb * ATT_SZ + abase + k0 + 16;
                float4 t0 = *(const float4*)p;
                float4 t1 = *(const float4*)(p + 4);
                a0.x += t0.x; a0.y += t0.y; a0.z += t0.z; a0.w += t0.w;
                a1.x += t1.x; a1.y += t1.y; a1.z += t1.z; a1.w += t1.w;
            }
            w = *(const float4*)(Wb + (size_t)(k0 + 16) * DM);
        }
#pragma unroll
        for (int kk = 0; kk < 16; kk++) {
            float4 a4 = *(const float4*)&As[buf][kk][ty << 2];
            float4 b4 = *(const float4*)&Ws[buf][kk][tx << 2];
            acc[0][0] = fmaf(a4.x, b4.x, acc[0][0]);
            acc[0][1] = fmaf(a4.x, b4.y, acc[0][1]);
            acc[0][2] = fmaf(a4.x, b4.z, acc[0][2]);
            acc[0][3] = fmaf(a4.x, b4.w, acc[0][3]);
            acc[1][0] = fmaf(a4.y, b4.x, acc[1][0]);
            acc[1][1] = fmaf(a4.y, b4.y, acc[1][1]);
            acc[1][2] = fmaf(a4.y, b4.z, acc[1][2]);
            acc[1][3] = fmaf(a4.y, b4.w, acc[1][3]);
            acc[2][0] = fmaf(a4.z, b4.x, acc[2][0]);
            acc[2][1] = fmaf(a4.z, b4.y, acc[2][1]);
            acc[2][2] = fmaf(a4.z, b4.z, acc[2][2]);
            acc[2][3] = fmaf(a4.z, b4.w, acc[2][3]);
            acc[3][0] = fmaf(a4.w, b4.x, acc[3][0]);
            acc[3][1] = fmaf(a4.w, b4.y, acc[3][1]);
            acc[3][2] = fmaf(a4.w, b4.z, acc[3][2]);
            acc[3][3] = fmaf(a4.w, b4.w, acc[3][3]);
        }
        buf ^= 1;
    }

    // epilogue: fused bias, direct write to y
#pragma unroll
    for (int i = 0; i < 4; i++) {
        int m = m0 + (ty << 2) + i;
        int n = n0 + (tx << 2);
        float4 bb = *(const float4*)(bo + n);
        *(float4*)&y[(size_t)m * DM + n] =
            make_float4(acc[i][0] + bb.x, acc[i][1] + bb.y,
                        acc[i][2] + bb.z, acc[i][3] + bb.w);
    }
}

// ---------------- launch ---------------------------------------------------
extern "C" void kernel_launch(void* const* d_in, const int* in_sizes, int n_in,
                              void* d_out, int out_size)
{
    const float* x  = (const float*)d_in[0];
    const float* Wf = (const float*)d_in[1];
    const float* bf = (const float*)d_in[2];
    const float* Wp = (const float*)d_in[3];
    const float* bp = (const float*)d_in[4];
    const float* Wa = (const float*)d_in[5];
    const float* ba = (const float*)d_in[6];
    const float* Wv = (const float*)d_in[7];
    const float* bv = (const float*)d_in[8];
    const float* Wo = (const float*)d_in[9];
    const float* bo = (const float*)d_in[10];
    float* y = (float*)d_out;

    proj3_kernel<<<dim3(28, 16), 128>>>(x, Wf, bf, Wp, bp, Wa, ba, Wv, bv);
    attn8_kernel<<<dim3(16, 8, 8), 256>>>();
    outp8_kernel<<<dim3(16, 16), 128>>>(Wo, bo, y);
}

// round 7
// speedup vs baseline: 1.5080x; 1.5080x over previous
#include <cuda_runtime.h>

#define TL 512
#define WN 16
#define HD 64
#define DM 512
#define ATT_SZ (1024 * DM)

#define INV2PI 0.15915494309189535f
#define MAGIC  12582912.0f            // 1.5 * 2^23
#define C2PI_A 6.2831854820251465f

typedef unsigned long long u64;

// ---------------- f32x2 packed helpers (Blackwell) -------------------------
__device__ __forceinline__ u64 pk2(float x, float y) {
    u64 r;
    asm("mov.b64 %0, {%1, %2};" : "=l"(r)
        : "r"(__float_as_uint(x)), "r"(__float_as_uint(y)));
    return r;
}
__device__ __forceinline__ u64 dup2(float x) { return pk2(x, x); }
__device__ __forceinline__ void up2(u64 v, float& x, float& y) {
    unsigned a, b;
    asm("mov.b64 {%0, %1}, %2;" : "=r"(a), "=r"(b) : "l"(v));
    x = __uint_as_float(a); y = __uint_as_float(b);
}
__device__ __forceinline__ u64 f2fma(u64 a, u64 b, u64 c) {
    u64 d;
    asm("fma.rn.f32x2 %0, %1, %2, %3;" : "=l"(d) : "l"(a), "l"(b), "l"(c));
    return d;
}
__device__ __forceinline__ u64 f2add(u64 a, u64 b) {
    u64 d;
    asm("add.rn.f32x2 %0, %1, %2;" : "=l"(d) : "l"(a), "l"(b));
    return d;
}
__device__ __forceinline__ u64 f2mul(u64 a, u64 b) {
    u64 d;
    asm("mul.rn.f32x2 %0, %1, %2;" : "=l"(d) : "l"(a), "l"(b));
    return d;
}

// 4x4 micro-tile step: acc2[i][0] += {a_i,a_i}*{b0,b1}, acc2[i][1] += {a_i,a_i}*{b2,b3}
__device__ __forceinline__ void mm4x4(const float4& a4, const ulonglong2& bb,
                                      u64 acc2[4][2]) {
    u64 t;
    t = dup2(a4.x); acc2[0][0] = f2fma(t, bb.x, acc2[0][0]);
                    acc2[0][1] = f2fma(t, bb.y, acc2[0][1]);
    t = dup2(a4.y); acc2[1][0] = f2fma(t, bb.x, acc2[1][0]);
                    acc2[1][1] = f2fma(t, bb.y, acc2[1][1]);
    t = dup2(a4.z); acc2[2][0] = f2fma(t, bb.x, acc2[2][0]);
                    acc2[2][1] = f2fma(t, bb.y, acc2[2][1]);
    t = dup2(a4.w); acc2[3][0] = f2fma(t, bb.x, acc2[3][0]);
                    acc2[3][1] = f2fma(t, bb.y, acc2[3][1]);
}

// ---------------- static scratch (no allocation) ----------------------------
__device__ float g_freq [16*TL*WN];   // [bh][t][w]
__device__ float g_phase[16*TL*WN];
__device__ float g_amp  [16*TL*WN];
__device__ float g_v    [16*TL*HD];   // [bh][t][d]
__device__ float g_att4 [4*ATT_SZ];   // attn@V partials, 4 k-splits

// ---------------- stage 1: projections, 64x64, 256 thr, 224 CTAs -----------
// grid (14, 16): n-tiles 0-1 freq, 2-3 phase, 4-5 amp, 6-13 v
__global__ __launch_bounds__(256)
void proj2_kernel(const float* __restrict__ x,
                  const float* __restrict__ Wf, const float* __restrict__ bf,
                  const float* __restrict__ Wp, const float* __restrict__ bp,
                  const float* __restrict__ Wa, const float* __restrict__ ba,
                  const float* __restrict__ Wv, const float* __restrict__ bv)
{
    __shared__ float As[2][16][68];
    __shared__ float Ws[2][16][68];

    const int nt = blockIdx.x;
    const int m0 = blockIdx.y * 64;
    const float* W; const float* bias; int ldw, nc0, kind;
    if      (nt < 2) { W = Wf; bias = bf; ldw = 128; nc0 = nt*64;       kind = 0; }
    else if (nt < 4) { W = Wp; bias = bp; ldw = 128; nc0 = nt*64 - 128; kind = 1; }
    else if (nt < 6) { W = Wa; bias = ba; ldw = 128; nc0 = nt*64 - 256; kind = 2; }
    else             { W = Wv; bias = bv; ldw = 512; nc0 = nt*64 - 384; kind = 3; }

    const int tid = threadIdx.x;
    const int lm  = tid >> 2;          // A row within tile (0..63)
    const int lk4 = (tid & 3) << 2;    // A k offset (0,4,8,12)
    const int lkk = tid >> 4;          // W k row (0..15)
    const int ln4 = (tid & 15) << 2;   // W n offset
    const int tx  = tid & 15;
    const int ty  = tid >> 4;

    const float* Ar = x + (size_t)(m0 + lm) * DM + lk4;
    const float* Wb = W + (size_t)lkk * ldw + nc0 + ln4;

    float4 a = *(const float4*)(Ar);
    float4 w = *(const float4*)(Wb);

    u64 acc2[4][2] = {};
    int buf = 0;
#pragma unroll 1
    for (int k0 = 0; k0 < 512; k0 += 16) {
        As[buf][lk4 + 0][lm] = a.x;
        As[buf][lk4 + 1][lm] = a.y;
        As[buf][lk4 + 2][lm] = a.z;
        As[buf][lk4 + 3][lm] = a.w;
        *(float4*)&Ws[buf][lkk][ln4] = w;
        __syncthreads();
        if (k0 + 16 < 512) {
            a = *(const float4*)(Ar + k0 + 16);
            w = *(const float4*)(Wb + (size_t)(k0 + 16) * ldw);
        }
#pragma unroll
        for (int kk = 0; kk < 16; kk++) {
            float4 a4 = *(const float4*)&As[buf][kk][ty << 2];
            ulonglong2 bb = *(const ulonglong2*)&Ws[buf][kk][tx << 2];
            mm4x4(a4, bb, acc2);
        }
        buf ^= 1;
    }

#pragma unroll
    for (int i = 0; i < 4; i++) {
        float c0, c1, c2, c3;
        up2(acc2[i][0], c0, c1);
        up2(acc2[i][1], c2, c3);
        float cr[4] = {c0, c1, c2, c3};
#pragma unroll
        for (int j = 0; j < 4; j++) {
            int m = m0 + (ty << 2) + i;
            int n = nc0 + (tx << 2) + j;
            float c = cr[j] + bias[n];
            int b = m >> 9, t = m & 511;
            if (kind == 3) {
                int h = n >> 6, d = n & 63;
                g_v[(((size_t)(b*8 + h) * TL) + t) * HD + d] = c;
            } else {
                int h = n >> 4, w_ = n & 15;
                size_t idx = (((size_t)(b*8 + h) * TL) + t) * WN + w_;
                if (kind == 0)      g_freq[idx]  = c;
                else if (kind == 1) g_phase[idx] = c;
                else {
                    float sp = fmaxf(c, 0.0f) + log1pf(expf(-fabsf(c)));
                    g_amp[idx] = sp + 1e-8f;
                }
            }
        }
    }
}

// ---------------- stage 2: interference attention, tiled -------------------
// grid (16 bh, 8 q-tiles reversed, 4 k-splits), 256 threads
__global__ __launch_bounds__(256, 2)
void attn4_kernel()
{
    __shared__ float s_fpa[64 * 52];   // per k row: 16 (-f) | 16 (-p) | 16 a | pad
    __shared__ float s_s2p[64 * 4];    // per k row: 4 partial sums of a^2
    __shared__ float s_att[64 * 68];   // [k][q], transposed
    __shared__ float s_v  [64 * 68];   // [k][d]

    const int bh = blockIdx.x;               // b*8+h
    const int qt = 7 - blockIdx.y;           // heavy q-tiles launch first
    const int s  = blockIdx.z;               // k-split (0..3)
    const int tid = threadIdx.x;
    const int qa = tid >> 2;                 // phase A q row (0..63)
    const int g  = tid & 3;                  // phase A k lane
    const int ty = tid >> 4;                 // phase B q group
    const int tx = tid & 15;                 // phase B d group
    const int qglob = qt * 64 + qa;
    const int b = bh >> 3, h = bh & 7;

    // q-side params in packed registers (pairs come free from 128-bit loads)
    u64 fq2[8], pq2[8], aq2[8];
    {
        const ulonglong2* f2 = (const ulonglong2*)(g_freq  + (((size_t)bh*TL) + qglob) * WN);
        const ulonglong2* p2 = (const ulonglong2*)(g_phase + (((size_t)bh*TL) + qglob) * WN);
        const ulonglong2* a2 = (const ulonglong2*)(g_amp   + (((size_t)bh*TL) + qglob) * WN);
#pragma unroll
        for (int i = 0; i < 4; i++) {
            ulonglong2 t;
            t = f2[i]; fq2[2*i] = t.x; fq2[2*i+1] = t.y;
            t = p2[i]; pq2[2*i] = t.x; pq2[2*i+1] = t.y;
            t = a2[i]; aq2[2*i] = t.x; aq2[2*i+1] = t.y;
        }
    }
    float s2q;
    {
        u64 s2 = 0ull;   // {0.f, 0.f}
#pragma unroll
        for (int i = 0; i < 8; i++) s2 = f2fma(aq2[i], aq2[i], s2);
        float lo, hi; up2(s2, lo, hi); s2q = lo + hi;
    }

    const u64 inv2pi2 = dup2(INV2PI);
    const u64 magic2  = dup2(MAGIC);
    const u64 nmagic2 = dup2(-MAGIC);
    const u64 nc2pi2  = dup2(-C2PI_A);

    u64 acc2[4][2] = {};

#pragma unroll 1
    for (int kt = s * 64; kt < (qt + 1) * 64; kt += 256) {
        __syncthreads();   // protect smem reuse from previous phase B
        // ---- stage k-tile: negated f/p, amp, per-row a^2 partials, V ----
        {
            int row = tid >> 2, c4 = (tid & 3) << 2;
            size_t base = ((size_t)bh * TL + (kt + row)) * WN + c4;
            float4 f = *(const float4*)(g_freq  + base);
            float4 p = *(const float4*)(g_phase + base);
            float4 a = *(const float4*)(g_amp   + base);
            *(float4*)&s_fpa[row*52 +      c4] = make_float4(-f.x, -f.y, -f.z, -f.w);
            *(float4*)&s_fpa[row*52 + 16 + c4] = make_float4(-p.x, -p.y, -p.z, -p.w);
            *(float4*)&s_fpa[row*52 + 32 + c4] = a;
            s_s2p[row*4 + (tid & 3)] = a.x*a.x + a.y*a.y + a.z*a.z + a.w*a.w;
#pragma unroll
            for (int i = 0; i < 4; i++) {
                int l = tid + i * 256;
                int r = l >> 4, cc = (l & 15) << 2;
                *(float4*)&s_v[r*68 + cc] =
                    *(const float4*)(g_v + ((size_t)bh*TL + (kt + r)) * HD + cc);
            }
        }
        __syncthreads();

        // ---- phase A: attn tile (f32x2 wave pairs) ----
#pragma unroll 1
        for (int j = 0; j < 16; j++) {
            int kl = g + (j << 2);
            int kg = kt + kl;
            float attv = 0.f;
            if (kg <= qglob) {
                const float dtv = (float)(qglob - kg);
                const u64 dt2 = dup2(dtv);
                const float* fk = &s_fpa[kl * 52];
                float4 s2p = *(const float4*)&s_s2p[kl * 4];
                float s2k = (s2p.x + s2p.y) + (s2p.z + s2p.w);
                u64 cacc2 = 0ull, dacc2 = 0ull;
#pragma unroll
                for (int g4 = 0; g4 < 4; g4++) {
                    ulonglong2 nf = *(const ulonglong2*)(fk +      (g4 << 2));
                    ulonglong2 np = *(const ulonglong2*)(fk + 16 + (g4 << 2));
                    ulonglong2 aa = *(const ulonglong2*)(fk + 32 + (g4 << 2));
#pragma unroll
                    for (int half = 0; half < 2; half++) {
                        int wp = 2*g4 + half;
                        u64 nfp = half ? nf.y : nf.x;
                        u64 npp = half ? np.y : np.x;
                        u64 aap = half ? aa.y : aa.x;
                        u64 dw  = f2add(fq2[wp], nfp);
                        u64 dp  = f2add(pq2[wp], npp);
                        u64 arg = f2fma(dw, dt2, dp);
                        u64 tr  = f2fma(arg, inv2pi2, magic2);
                        u64 nn  = f2add(tr, nmagic2);
                        u64 rr  = f2fma(nn, nc2pi2, arg);
                        float r0, r1; up2(rr, r0, r1);
                        u64 cs  = pk2(__cosf(r0), __cosf(r1));
                        u64 pp  = f2mul(aq2[wp], aap);
                        dacc2 = f2add(dacc2, pp);
                        cacc2 = f2fma(pp, cs, cacc2);
                    }
                }
                float c0, c1, d0, d1;
                up2(cacc2, c0, c1); up2(dacc2, d0, d1);
                float cacc = c0 + c1, dacc = d0 + d1;
                float S  = s2q + s2k;
                float it = fmaf(2.f, cacc, S);
                float en = fmaf(2.f, dacc, S) + 1e-8f;
                attv = __fdividef(it, en);
            }
            s_att[kl * 68 + qa] = attv;
        }
        __syncthreads();

        // ---- phase B: acc += attn_tile @ V_tile (f32x2) ----
#pragma unroll 4
        for (int kk = 0; kk < 64; kk++) {
            float4 a4 = *(const float4*)&s_att[kk*68 + (ty << 2)];
            ulonglong2 vv = *(const ulonglong2*)&s_v[kk*68 + (tx << 2)];
            mm4x4(a4, vv, acc2);
        }
    }

    // ---- epilogue: write 4x4 block (zeros if this split had no tiles) ----
    float* dst = g_att4 + (size_t)s * ATT_SZ;
#pragma unroll
    for (int i = 0; i < 4; i++) {
        float c0, c1, c2, c3;
        up2(acc2[i][0], c0, c1);
        up2(acc2[i][1], c2, c3);
        int row = qt * 64 + (ty << 2) + i;
        *(float4*)&dst[((size_t)(b * TL + row)) * DM + h * HD + (tx << 2)] =
            make_float4(c0, c1, c2, c3);
    }
}

// ---------------- stage 3: output projection (4-way A-sum, fused bias) -----
__global__ __launch_bounds__(256)
void outp4_kernel(const float* __restrict__ Wo,
                  const float* __restrict__ bo,
                  float* __restrict__ y)
{
    __shared__ float As[2][16][68];
    __shared__ float Ws[2][16][68];
    const int n0 = blockIdx.x * 64;
    const int m0 = blockIdx.y * 64;
    const int tid = threadIdx.x;
    const int lm  = tid >> 2;
    const int lk4 = (tid & 3) << 2;
    const int lkk = tid >> 4;
    const int ln4 = (tid & 15) << 2;
    const int tx  = tid & 15;
    const int ty  = tid >> 4;

    const size_t abase = (size_t)(m0 + lm) * DM + lk4;
    const float* Wb = Wo + (size_t)lkk * DM + n0 + ln4;

    u64 acc2[4][2] = {};

    // prefetch chunk 0: 4-buffer packed sum
    ulonglong2 a;
    {
        ulonglong2 a0 = *(const ulonglong2*)(g_att4 + 0*ATT_SZ + abase);
        ulonglong2 a1 = *(const ulonglong2*)(g_att4 + 1*ATT_SZ + abase);
        ulonglong2 a2 = *(const ulonglong2*)(g_att4 + 2*ATT_SZ + abase);
        ulonglong2 a3 = *(const ulonglong2*)(g_att4 + 3*ATT_SZ + abase);
        a.x = f2add(f2add(a0.x, a1.x), f2add(a2.x, a3.x));
        a.y = f2add(f2add(a0.y, a1.y), f2add(a2.y, a3.y));
    }
    float4 w = *(const float4*)(Wb);

    int buf = 0;
#pragma unroll 1
    for (int k0 = 0; k0 < 512; k0 += 16) {
        {
            float s0, s1, s2, s3;
            up2(a.x, s0, s1); up2(a.y, s2, s3);
            As[buf][lk4 + 0][lm] = s0;
            As[buf][lk4 + 1][lm] = s1;
            As[buf][lk4 + 2][lm] = s2;
            As[buf][lk4 + 3][lm] = s3;
        }
        *(float4*)&Ws[buf][lkk][ln4] = w;
        __syncthreads();
        if (k0 + 16 < 512) {
            ulonglong2 a0 = *(const ulonglong2*)(g_att4 + 0*ATT_SZ + abase + k0 + 16);
            ulonglong2 a1 = *(const ulonglong2*)(g_att4 + 1*ATT_SZ + abase + k0 + 16);
            ulonglong2 a2 = *(const ulonglong2*)(g_att4 + 2*ATT_SZ + abase + k0 + 16);
            ulonglong2 a3 = *(const ulonglong2*)(g_att4 + 3*ATT_SZ + abase + k0 + 16);
            a.x = f2add(f2add(a0.x, a1.x), f2add(a2.x, a3.x));
            a.y = f2add(f2add(a0.y, a1.y), f2add(a2.y, a3.y));
            w = *(const float4*)(Wb + (size_t)(k0 + 16) * DM);
        }
#pragma unroll
        for (int kk = 0; kk < 16; kk++) {
            float4 a4 = *(const float4*)&As[buf][kk][ty << 2];
            ulonglong2 bb = *(const ulonglong2*)&Ws[buf][kk][tx << 2];
            mm4x4(a4, bb, acc2);
        }
        buf ^= 1;
    }

    // epilogue: fused bias, direct write to y
#pragma unroll
    for (int i = 0; i < 4; i++) {
        float c0, c1, c2, c3;
        up2(acc2[i][0], c0, c1);
        up2(acc2[i][1], c2, c3);
        int m = m0 + (ty << 2) + i;
        int n = n0 + (tx << 2);
        float4 bb = *(const float4*)(bo + n);
        *(float4*)&y[(size_t)m * DM + n] =
            make_float4(c0 + bb.x, c1 + bb.y, c2 + bb.z, c3 + bb.w);
    }
}

// ---------------- launch ----------------------------------------------------
extern "C" void kernel_launch(void* const* d_in, const int* in_sizes, int n_in,
                              void* d_out, int out_size)
{
    const float* x  = (const float*)d_in[0];
    const float* Wf = (const float*)d_in[1];
    const float* bf = (const float*)d_in[2];
    const float* Wp = (const float*)d_in[3];
    const float* bp = (const float*)d_in[4];
    const float* Wa = (const float*)d_in[5];
    const float* ba = (const float*)d_in[6];
    const float* Wv = (const float*)d_in[7];
    const float* bv = (const float*)d_in[8];
    const float* Wo = (const float*)d_in[9];
    const float* bo = (const float*)d_in[10];
    float* y = (float*)d_out;

    proj2_kernel<<<dim3(14, 16), 256>>>(x, Wf, bf, Wp, bp, Wa, ba, Wv, bv);
    attn4_kernel<<<dim3(16, 8, 4), 256>>>();
    outp4_kernel<<<dim3(8, 16), 256>>>(Wo, bo, y);
}